// round 17
// baseline (speedup 1.0000x reference)
#include <cuda_runtime.h>
#include <cuda_bf16.h>
#include <math.h>
#include <stdint.h>

#define NP   8192
#define DIM  128
#define NSTR 64               // 64 stripes of 128 rows
#define NCTA 148
#define NTHR 512

#define KLN2F  6.1996966f             // ln2/(sqrt_c*T)
#define KFULLF 8.944271909999159f     // 1/(sqrt_c*T)
#define TEMPF  0.5f
#define LG09   -0.14801175f           // lg2(0.9025)
// Taylor of lg2(1+d), d = dn-1 in [-0.0975, 0.1025]
#define PC1  1.44269504f
#define PC2 -0.72134752f
#define PC3  0.48089835f
#define PC4 -0.36067376f

#define LDS_ROW 144           // 128 fp8 + 16 pad (keeps 16B-slot distinctness mod 128)

#define OFF_A0 0
#define OFF_A1 18432
#define OFF_B0 36864
#define OFF_B1 55296
#define OFF_B2 73728
#define SMEM_REQ 92160

__device__ uint8_t g_f8[NP * DIM];         // normalized features, e4m3
__device__ int    g_lab[NP];               // packed (pl<<16)|sl
__device__ float2 g_stats2[NP];            // x=T (sum exp, excl diag), y=Sum L2(pos)

// ---------------- PTX helpers (base sm_103-safe) ----------------
__device__ __forceinline__ uint32_t smem_u32(const void* p) {
    uint32_t a;
    asm("{ .reg .u64 t; cvta.to.shared.u64 t, %1; cvt.u32.u64 %0, t; }" : "=r"(a) : "l"(p));
    return a;
}
__device__ __forceinline__ float f_sqrt(float x){float r;asm("sqrt.approx.f32 %0,%1;":"=f"(r):"f"(x));return r;}
__device__ __forceinline__ float f_lg2(float x){float r;asm("lg2.approx.f32 %0,%1;":"=f"(r):"f"(x));return r;}
__device__ __forceinline__ float f_ex2(float x){float r;asm("ex2.approx.f32 %0,%1;":"=f"(r):"f"(x));return r;}

// pack 4 consecutive floats -> 4 e4m3 bytes (byte0 = a ... byte3 = d)
__device__ __forceinline__ uint32_t pack4_e4m3(float a, float b, float c, float d){
    uint16_t lo, hi;
    asm("cvt.rn.satfinite.e4m3x2.f32 %0, %1, %2;" : "=h"(lo) : "f"(b), "f"(a));
    asm("cvt.rn.satfinite.e4m3x2.f32 %0, %1, %2;" : "=h"(hi) : "f"(d), "f"(c));
    return (uint32_t)lo | ((uint32_t)hi << 16);
}

// vector reductions to global (sm_90+)
__device__ __forceinline__ void red2g(float* a, float x, float y){
    asm volatile("red.global.add.v2.f32 [%0],{%1,%2};" :: "l"(a), "f"(x), "f"(y) : "memory");
}
__device__ __forceinline__ void red4g(float* a, float x, float y, float z, float w){
    asm volatile("red.global.add.v4.f32 [%0],{%1,%2,%3,%4};" :: "l"(a), "f"(x), "f"(y), "f"(z), "f"(w) : "memory");
}

__device__ __forceinline__ void cp16(uint32_t dst, const void* src) {
    asm volatile("cp.async.cg.shared.global [%0], [%1], 16;" :: "r"(dst), "l"(src) : "memory");
}
#define CP_COMMIT() asm volatile("cp.async.commit_group;" ::: "memory")
#define CP_WAIT(n)  asm volatile("cp.async.wait_group %0;" :: "n"(n) : "memory")

__device__ __forceinline__ void ldsm4(uint32_t& r0, uint32_t& r1, uint32_t& r2, uint32_t& r3,
                                      uint32_t addr) {
    asm volatile("ldmatrix.sync.aligned.m8n8.x4.shared.b16 {%0,%1,%2,%3}, [%4];"
                 : "=r"(r0), "=r"(r1), "=r"(r2), "=r"(r3) : "r"(addr));
}
// fp8 e4m3 MMA: m16n8k32, fragments = f16 m16n8k16 layout with k-pairs per 16-bit slot
__device__ __forceinline__ void mma16832(float* c, const uint32_t* a, const uint32_t* b) {
    asm volatile(
        "mma.sync.aligned.m16n8k32.row.col.f32.e4m3.e4m3.f32 "
        "{%0,%1,%2,%3}, {%4,%5,%6,%7}, {%8,%9}, {%0,%1,%2,%3};"
        : "+f"(c[0]), "+f"(c[1]), "+f"(c[2]), "+f"(c[3])
        : "r"(a[0]), "r"(a[1]), "r"(a[2]), "r"(a[3]), "r"(b[0]), "r"(b[1]));
}

// ---------------------------------------------------------------------------
// 2 rows per warp; output e4m3
__global__ void norm_kernel(const float* __restrict__ feat,
                            const int* __restrict__ pl, const int* __restrict__ sl) {
    int r0   = blockIdx.x * 16 + (threadIdx.x >> 5) * 2;
    int r1   = r0 + 1;
    int lane = threadIdx.x & 31;
    float4 v0 = ((const float4*)(feat + r0 * DIM))[lane];
    float4 v1 = ((const float4*)(feat + r1 * DIM))[lane];
    float s0 = v0.x*v0.x + v0.y*v0.y + v0.z*v0.z + v0.w*v0.w;
    float s1 = v1.x*v1.x + v1.y*v1.y + v1.z*v1.z + v1.w*v1.w;
    #pragma unroll
    for (int o = 16; o; o >>= 1) {
        s0 += __shfl_xor_sync(0xffffffffu, s0, o);
        s1 += __shfl_xor_sync(0xffffffffu, s1, o);
    }
    float i0 = 1.0f / fmaxf(sqrtf(s0), 1e-12f);
    float i1 = 1.0f / fmaxf(sqrtf(s1), 1e-12f);
    ((uint32_t*)g_f8)[r0 * 32 + lane] = pack4_e4m3(v0.x*i0, v0.y*i0, v0.z*i0, v0.w*i0);
    ((uint32_t*)g_f8)[r1 * 32 + lane] = pack4_e4m3(v1.x*i1, v1.y*i1, v1.z*i1, v1.w*i1);
    if (lane == 0) g_lab[r0] = (pl[r0] << 16) | (sl[r0] & 0xFFFF);
    if (lane == 1) g_lab[r1] = (pl[r1] << 16) | (sl[r1] & 0xFFFF);
    if (threadIdx.x < 16) g_stats2[blockIdx.x * 16 + threadIdx.x] = make_float2(0.f, 0.f);
}

// cp.async one 128x128 fp8 tile (128B gmem rows) into padded SMEM (512 thr)
__device__ __forceinline__ void cp_tile(uint32_t udst, const char* gsrc, int tid) {
    #pragma unroll
    for (int it = 0; it < 2; it++) {
        int idx = tid + it * NTHR;      // 0..1023
        int row = idx >> 3;
        int ch  = idx & 7;
        cp16(udst + row * LDS_ROW + ch * 16, gsrc + row * 128 + ch * 16);
    }
}

// ---------------------------------------------------------------------------
__global__ void __launch_bounds__(NTHR, 1)
pair_kernel() {
    extern __shared__ __align__(16) char sm[];
    const uint32_t ub = smem_u32(sm);
    const uint32_t boffs3[3] = {ub + OFF_B0, ub + OFF_B1, ub + OFF_B2};

    const int tid  = threadIdx.x;
    const int wid  = tid >> 5;
    const int lane = tid & 31;
    const int wm   = wid & 3;
    const int wn   = wid >> 2;
    const char* gsrc = (const char*)g_f8;

    const int cta  = blockIdx.x;
    const int t0   = cta * 14 + (cta < 8 ? cta : 8);
    const int tend = t0 + 14 + (cta < 8 ? 1 : 0);

    int I = 0, base = 0;
    while (base + (NSTR - I) <= t0) { base += NSTR - I; I++; }
    int J = I + (t0 - base);

    cp_tile(ub + OFF_A0, gsrc + (size_t)I * 128 * 128, tid);
    cp_tile(boffs3[0],   gsrc + (size_t)J * 128 * 128, tid);
    CP_COMMIT();
    int abuf = 0;

    // ldmatrix lane offsets (byte offsets; 16B groups cover k-pairs 0-7 / 8-15 of a 32B k-step)
    const int g  = lane >> 3;
    const int lr = lane & 7;
    uint32_t aoff[2], boff[2];
    #pragma unroll
    for (int a = 0; a < 2; a++)
        aoff[a] = (uint32_t)((wm * 32 + a * 16 + (g & 1) * 8 + lr) * LDS_ROW + (g >> 1) * 16);
    #pragma unroll
    for (int p = 0; p < 2; p++)
        boff[p] = (uint32_t)((wn * 32 + p * 16 + (g >> 1) * 8 + lr) * LDS_ROW + (g & 1) * 16);

    int grow[4], pk[4];
    #pragma unroll
    for (int rr = 0; rr < 4; rr++) {
        grow[rr] = I * 128 + wm * 32 + (rr >> 1) * 16 + (rr & 1) * 8 + (lane >> 2);
        pk[rr]   = g_lab[grow[rr]];
    }
    float T[4] = {0,0,0,0}, Ap[4] = {0,0,0,0};

    const int2* glab2 = (const int2*)g_lab;

    for (int t = t0; t < tend; t++) {
        int In = I, Jn = J + 1;
        if (Jn == NSTR) { In = I + 1; Jn = In; }
        const bool last = (t + 1 >= tend);
        const int  slot = (t - t0) % 3;

        if (!last) {
            cp_tile(boffs3[(t - t0 + 1) % 3], gsrc + (size_t)Jn * 128 * 128, tid);
            if (In != I)
                cp_tile(ub + (abuf ? OFF_A0 : OFF_A1), gsrc + (size_t)In * 128 * 128, tid);
            CP_COMMIT();
            CP_WAIT(1);
        } else {
            CP_WAIT(0);
        }
        __syncthreads();

        const uint32_t uA = ub + (abuf ? OFF_A1 : OFF_A0);
        const uint32_t uB = boffs3[slot];

        float acc[2][4][4];
        #pragma unroll
        for (int a = 0; a < 2; a++)
            #pragma unroll
            for (int b = 0; b < 4; b++)
                #pragma unroll
                for (int j = 0; j < 4; j++) acc[a][b][j] = 0.0f;

        // ---- FP8 MMA: 4 k-steps of 32 fp8 (32 bytes); n-half outer ----
        #pragma unroll
        for (int h = 0; h < 2; h++) {
            #pragma unroll
            for (int ks = 0; ks < 4; ks++) {
                const uint32_t kb = (uint32_t)(ks * 32);
                uint32_t af[2][4], bf[2][2];
                #pragma unroll
                for (int a = 0; a < 2; a++)
                    ldsm4(af[a][0], af[a][1], af[a][2], af[a][3], uA + aoff[a] + kb);
                ldsm4(bf[0][0], bf[0][1], bf[1][0], bf[1][1], uB + boff[h] + kb);
                #pragma unroll
                for (int a = 0; a < 2; a++) {
                    mma16832(acc[a][2*h],     af[a], bf[0]);
                    mma16832(acc[a][2*h + 1], af[a], bf[1]);
                }
            }
        }

        // ---- epilogue (unchanged; acc layout identical to bf16 path) ----
        const int  jt = J * 128;
        const bool offdiag = (J != I);
        float TcB[4][2], AcB[4][2];
        #pragma unroll
        for (int b = 0; b < 4; b++) {
            const int li  = wn * 32 + b * 8 + ((lane & 3) << 1);
            const int2 pk2 = glab2[(jt + li) >> 1];

            float s8[8], sq8[8], l18[8], L28[8], e8[8];
            #pragma unroll
            for (int i = 0; i < 8; i++) s8[i] = acc[i >> 2][b][i & 3];

            #pragma unroll
            for (int i = 0; i < 8; i++) {          // stage 1: sqrt
                float q  = fmaf(-11.025f, s8[i], 10.025f);
                float t2 = fmaf(s8[i], s8[i], q);
                sq8[i] = f_sqrt(fmaxf(t2, 0.0f));
            }
            #pragma unroll
            for (int i = 0; i < 8; i++) {          // stage 2: lg2
                float dn  = fmaf(-0.1f, s8[i], 1.0025f);
                l18[i] = f_lg2(fmaf(0.1f, sq8[i], dn));
            }
            #pragma unroll
            for (int i = 0; i < 8; i++) {          // stage 3: poly + ex2
                float d  = fmaf(-0.1f, s8[i], 0.0025f);   // dn - 1
                float in3 = fmaf(d, PC4, PC3);
                float in2 = fmaf(d, in3, PC2);
                float in1 = fmaf(d, in2, PC1);
                float pc  = fmaf(d, in1, LG09);           // lg2(0.9025*dn)
                float L2  = fmaf(2.0f, l18[i], -pc);
                L28[i] = L2;
                e8[i]  = f_ex2(-KFULLF * L2);
            }

            if (offdiag) {
                float Tc0 = 0.f, Ac0 = 0.f, Tc1 = 0.f, Ac1 = 0.f;
                #pragma unroll
                for (int i = 0; i < 8; i++) {
                    const int rr = (i >> 2) * 2 + ((i & 3) >> 1);
                    const int pkj = (i & 1) ? pk2.y : pk2.x;
                    unsigned dx = (unsigned)(pk[rr] ^ pkj);
                    bool sp = (dx < 0x10000u) | ((dx & 0xFFFFu) == 0u);
                    float lpos = sp ? L28[i] : 0.0f;
                    T[rr] += e8[i]; Ap[rr] += lpos;
                    if (i & 1) { Tc1 += e8[i]; Ac1 += lpos; }
                    else       { Tc0 += e8[i]; Ac0 += lpos; }
                }
                TcB[b][0] = Tc0; TcB[b][1] = Tc1;
                AcB[b][0] = Ac0; AcB[b][1] = Ac1;
            } else {
                #pragma unroll
                for (int i = 0; i < 8; i++) {
                    const int rr  = (i >> 2) * 2 + ((i & 3) >> 1);
                    const int col = jt + li + (i & 1);
                    const int pkj = (i & 1) ? pk2.y : pk2.x;
                    unsigned dx = (unsigned)(pk[rr] ^ pkj);
                    bool dg = (col == grow[rr]);
                    bool sp = ((dx < 0x10000u) | ((dx & 0xFFFFu) == 0u)) && !dg;
                    T[rr]  += dg ? 0.0f : e8[i];
                    Ap[rr] += sp ? L28[i] : 0.0f;
                }
            }
        }

        if (offdiag) {
            #pragma unroll
            for (int o = 4; o <= 16; o <<= 1) {
                #pragma unroll
                for (int b = 0; b < 4; b++) {
                    TcB[b][0] += __shfl_xor_sync(0xffffffffu, TcB[b][0], o);
                    AcB[b][0] += __shfl_xor_sync(0xffffffffu, AcB[b][0], o);
                    TcB[b][1] += __shfl_xor_sync(0xffffffffu, TcB[b][1], o);
                    AcB[b][1] += __shfl_xor_sync(0xffffffffu, AcB[b][1], o);
                }
            }
            if (lane < 4) {
                #pragma unroll
                for (int b = 0; b < 4; b++) {
                    const int li = wn * 32 + b * 8 + ((lane & 3) << 1);
                    red4g((float*)&g_stats2[jt + li],
                          TcB[b][0], AcB[b][0], TcB[b][1], AcB[b][1]);
                }
            }
        }

        // row-stat flush on stripe change / end
        if (last || In != I) {
            #pragma unroll
            for (int rr = 0; rr < 4; rr++) {
                float tr = T[rr], ar = Ap[rr];
                #pragma unroll
                for (int o = 1; o <= 2; o <<= 1) {
                    tr += __shfl_xor_sync(0xffffffffu, tr, o);
                    ar += __shfl_xor_sync(0xffffffffu, ar, o);
                }
                if ((lane & 3) == 0)
                    red2g((float*)&g_stats2[grow[rr]], tr, ar);
                T[rr] = 0.f; Ap[rr] = 0.f;
            }
            if (!last && In != I) {
                abuf ^= 1;
                #pragma unroll
                for (int rr = 0; rr < 4; rr++) {
                    grow[rr] = In * 128 + wm * 32 + (rr >> 1) * 16 + (rr & 1) * 8 + (lane >> 2);
                    pk[rr]   = g_lab[grow[rr]];
                }
            }
        }
        if (!last) { I = In; J = Jn; }
    }
}

// ---------------------------------------------------------------------------
// finalize: label histograms (num_pos) + row reduction -> scalar loss
__global__ void finalize_kernel(float* __restrict__ out) {
    __shared__ int hcp[32], hcs[16], hcj[512];
    __shared__ float ssum[32], scnt[32];
    int tid = threadIdx.x;  // 1024
    if (tid < 512) hcj[tid] = 0;
    if (tid < 32)  hcp[tid] = 0;
    if (tid < 16)  hcs[tid] = 0;
    __syncthreads();
    for (int i = tid; i < NP; i += 1024) {
        int pkv = g_lab[i];
        int p = pkv >> 16, s2 = pkv & 0xFFFF;
        atomicAdd(&hcp[p], 1);
        atomicAdd(&hcs[s2], 1);
        atomicAdd(&hcj[p * 16 + s2], 1);
    }
    __syncthreads();

    float sum = 0.0f, nv = 0.0f;
    for (int i = tid; i < NP; i += 1024) {
        int pkv = g_lab[i];
        int p = pkv >> 16, s2 = pkv & 0xFFFF;
        float np = (float)(hcp[p] + hcs[s2] - hcj[p * 16 + s2] - 1);
        float2 st = g_stats2[i];
        if (np > 0.0f) {
            float den = st.x + 1e-8f;
            sum += (-KLN2F * st.y - np * __logf(den)) / np;
            nv  += 1.0f;
        }
    }
    #pragma unroll
    for (int o = 16; o; o >>= 1) {
        sum += __shfl_xor_sync(0xffffffffu, sum, o);
        nv  += __shfl_xor_sync(0xffffffffu, nv,  o);
    }
    if ((tid & 31) == 0) { ssum[tid >> 5] = sum; scnt[tid >> 5] = nv; }
    __syncthreads();
    if (tid < 32) {
        sum = ssum[tid]; nv = scnt[tid];
        #pragma unroll
        for (int o = 16; o; o >>= 1) {
            sum += __shfl_xor_sync(0xffffffffu, sum, o);
            nv  += __shfl_xor_sync(0xffffffffu, nv,  o);
        }
        if (tid == 0) {
            float loss = 0.0f;
            if (nv > 0.0f) loss = -sum / fmaxf(nv, 1.0f) * TEMPF;
            if (!isfinite(loss)) loss = 0.0f;
            out[0] = loss;
        }
    }
}

// ---------------------------------------------------------------------------
extern "C" void kernel_launch(void* const* d_in, const int* in_sizes, int n_in,
                              void* d_out, int out_size) {
    const float* feat = (const float*)d_in[0];
    const int*   pl   = (const int*)d_in[1];
    const int*   sl   = (const int*)d_in[2];
    float* out = (float*)d_out;

    cudaFuncSetAttribute(pair_kernel, cudaFuncAttributeMaxDynamicSharedMemorySize, SMEM_REQ);

    norm_kernel<<<NP / 16, 256>>>(feat, pl, sl);
    pair_kernel<<<NCTA, NTHR, SMEM_REQ>>>();
    finalize_kernel<<<1, 1024>>>(out);
}